// round 12
// baseline (speedup 1.0000x reference)
#include <cuda_runtime.h>
#include <math.h>
#include <stdint.h>

#define NR 3200
#define NA 320
#define TD 512
#define DD 128
#define H  128
#define B  8

#define NTF 134              // tf GEMM blocks, 24 rows each (3 rows/warp)
#define TROWS 24
#define NDF 10               // df GEMM blocks, 32 rows each (4 rows/warp)
#define NGEMM (NTF + NDF)    // 144 <= 148: one GEMM block per SM
#define KT  32               // k-tile for W staging

// dynamic smem for kA: tf: 24*512 A + 32*128 W = 16384 floats = 64 KB
#define DYN_FLOATS (TROWS * TD + KT * H)
#define DYN_BYTES  (DYN_FLOATS * 4)

// ---------------- scratch (device globals) ----------------------------------
__device__ float g_tf[NR * H];
__device__ float g_df[NA * H];
// statically initialized; finalize resets after use (graph replay safe)
__device__ int   g_smn[B] = {0x7F800000,0x7F800000,0x7F800000,0x7F800000,
                             0x7F800000,0x7F800000,0x7F800000,0x7F800000};
__device__ int   g_smx[B] = {0,0,0,0,0,0,0,0};
__device__ float g_dminf[B];
__device__ float g_invden[B];
__device__ int   g_as[B];
__device__ int   g_ae[B];
__device__ int   g_gemm_done = 0;

__device__ __forceinline__ int lowerb(const int* __restrict__ a, int n, int key) {
    int lo = 0, hi = n;
    while (lo < hi) { int m = (lo + hi) >> 1; if (a[m] < key) lo = m + 1; else hi = m; }
    return lo;
}

// =================== Kernel A: GEMMs + segment min/max ========================
__global__ void __launch_bounds__(256)
kA(const float* __restrict__ tfeat,
   const float* __restrict__ Wt,
   const float* __restrict__ bt,
   const float* __restrict__ dfeat,
   const float* __restrict__ Wd,
   const float* __restrict__ bd,
   const float* __restrict__ tpos,
   const float* __restrict__ dpos,
   const int* __restrict__ seg_res,
   const int* __restrict__ seg_atom) {
    extern __shared__ float buf[];
    __shared__ int  s_as8[B], s_ae8[B];
    __shared__ int  s_bmn[B], s_bmx[B];
    __shared__ bool isLast;

    const int t = threadIdx.x;
    const int w = t >> 5, lane = t & 31;
    const int bid = blockIdx.x;

    if (t < B) {
        s_as8[t] = lowerb(seg_atom, NA, t);
        s_ae8[t] = lowerb(seg_atom, NA, t + 1);
        s_bmn[t] = 0x7F800000;
        s_bmx[t] = 0;
    }
    __syncthreads();

    if (bid < NTF) {
        // ---- tf GEMM: 24 rows, 3 rows/warp, Wt k-tiled (KT=32) in smem ----
        float* sA = buf;                                            // 24*512 floats
        float4* sW4 = reinterpret_cast<float4*>(buf + TROWS * TD);  // 32*128 floats

        const int i0 = bid * TROWS;
        {
            float4* dst = reinterpret_cast<float4*>(sA);
            const float4 z = make_float4(0.f, 0.f, 0.f, 0.f);
            #pragma unroll
            for (int idx = t; idx < TROWS * TD / 4; idx += 256) {
                const int row = i0 + idx / (TD / 4);
                dst[idx] = (row < NR)
                    ? reinterpret_cast<const float4*>(tfeat)[(size_t)i0 * (TD / 4) + idx]
                    : z;
            }
        }

        const float* a0 = sA + (3 * w) * TD;
        const float* a1 = sA + (3 * w + 1) * TD;
        const float* a2 = sA + (3 * w + 2) * TD;
        const float4* W4 = reinterpret_cast<const float4*>(Wt);
        float4 acc0 = make_float4(0.f, 0.f, 0.f, 0.f);
        float4 acc1 = make_float4(0.f, 0.f, 0.f, 0.f);
        float4 acc2 = make_float4(0.f, 0.f, 0.f, 0.f);

        for (int kt = 0; kt < TD; kt += KT) {
            __syncthreads();
            #pragma unroll
            for (int idx = t; idx < KT * H / 4; idx += 256)
                sW4[idx] = W4[(size_t)kt * (H / 4) + idx];
            __syncthreads();
            #pragma unroll 8
            for (int k = 0; k < KT; k++) {
                float4 wv = sW4[k * 32 + lane];
                float x0 = a0[kt + k], x1 = a1[kt + k], x2 = a2[kt + k];
                acc0.x = fmaf(x0, wv.x, acc0.x); acc0.y = fmaf(x0, wv.y, acc0.y);
                acc0.z = fmaf(x0, wv.z, acc0.z); acc0.w = fmaf(x0, wv.w, acc0.w);
                acc1.x = fmaf(x1, wv.x, acc1.x); acc1.y = fmaf(x1, wv.y, acc1.y);
                acc1.z = fmaf(x1, wv.z, acc1.z); acc1.w = fmaf(x1, wv.w, acc1.w);
                acc2.x = fmaf(x2, wv.x, acc2.x); acc2.y = fmaf(x2, wv.y, acc2.y);
                acc2.z = fmaf(x2, wv.z, acc2.z); acc2.w = fmaf(x2, wv.w, acc2.w);
            }
        }
        float4 bb = reinterpret_cast<const float4*>(bt)[lane];
        acc0.x += bb.x; acc0.y += bb.y; acc0.z += bb.z; acc0.w += bb.w;
        acc1.x += bb.x; acc1.y += bb.y; acc1.z += bb.z; acc1.w += bb.w;
        acc2.x += bb.x; acc2.y += bb.y; acc2.z += bb.z; acc2.w += bb.w;
        {
            const int r0 = i0 + 3 * w;
            float4* gtf4 = reinterpret_cast<float4*>(g_tf);
            if (r0 + 0 < NR) gtf4[(size_t)(r0 + 0) * 32 + lane] = acc0;
            if (r0 + 1 < NR) gtf4[(size_t)(r0 + 1) * 32 + lane] = acc1;
            if (r0 + 2 < NR) gtf4[(size_t)(r0 + 2) * 32 + lane] = acc2;
        }

        // ---- per-row distance min/max -> smem seg reduce -> global atomics --
        #pragma unroll
        for (int r2 = 0; r2 < 3; r2++) {
            const int i = i0 + 3 * w + r2;
            if (i >= NR) break;
            const int b = seg_res[i];
            const int as = s_as8[b], ae = s_ae8[b];
            const float px = tpos[3 * i], py = tpos[3 * i + 1], pz = tpos[3 * i + 2];
            float mn = INFINITY, mx = 0.0f;
            for (int j = as + lane; j < ae; j += 32) {
                float dx = px - dpos[3 * j];
                float dy = py - dpos[3 * j + 1];
                float dz = pz - dpos[3 * j + 2];
                float d = sqrtf(dx * dx + dy * dy + dz * dz);
                mn = fminf(mn, d); mx = fmaxf(mx, d);
            }
            #pragma unroll
            for (int o = 16; o; o >>= 1) {
                mn = fminf(mn, __shfl_xor_sync(0xFFFFFFFFu, mn, o));
                mx = fmaxf(mx, __shfl_xor_sync(0xFFFFFFFFu, mx, o));
            }
            if (lane == 0) {
                atomicMin(&s_bmn[b], __float_as_int(mn));  // nonneg: int cmp == float cmp
                atomicMax(&s_bmx[b], __float_as_int(mx));
            }
        }
        __syncthreads();
        if (t < B) {
            if (s_bmn[t] != 0x7F800000) atomicMin(&g_smn[t], s_bmn[t]);
            if (s_bmx[t] != 0)          atomicMax(&g_smx[t], s_bmx[t]);
        }
    } else {
        // ---- df GEMM: 32 rows, 4 rows/warp, Wd k-tiled (KT=32) in smem ----
        float* sA = buf;                                          // 32*128 floats
        float4* sW4 = reinterpret_cast<float4*>(buf + 32 * DD);   // 32*128 floats

        const int i0 = (bid - NTF) * 32;
        {
            const float4* src = reinterpret_cast<const float4*>(dfeat + (size_t)i0 * DD);
            float4* dst = reinterpret_cast<float4*>(sA);
            #pragma unroll
            for (int idx = t; idx < 32 * DD / 4; idx += 256) dst[idx] = src[idx];
        }

        const float* a0 = sA + (4 * w) * DD;
        const float* a1 = sA + (4 * w + 1) * DD;
        const float* a2 = sA + (4 * w + 2) * DD;
        const float* a3 = sA + (4 * w + 3) * DD;
        const float4* W4 = reinterpret_cast<const float4*>(Wd);
        float4 acc0 = make_float4(0.f, 0.f, 0.f, 0.f);
        float4 acc1 = make_float4(0.f, 0.f, 0.f, 0.f);
        float4 acc2 = make_float4(0.f, 0.f, 0.f, 0.f);
        float4 acc3 = make_float4(0.f, 0.f, 0.f, 0.f);

        for (int kt = 0; kt < DD; kt += KT) {
            __syncthreads();
            #pragma unroll
            for (int idx = t; idx < KT * H / 4; idx += 256)
                sW4[idx] = W4[(size_t)kt * (H / 4) + idx];
            __syncthreads();
            #pragma unroll 8
            for (int k = 0; k < KT; k++) {
                float4 wv = sW4[k * 32 + lane];
                float x0 = a0[kt + k], x1 = a1[kt + k], x2 = a2[kt + k], x3 = a3[kt + k];
                acc0.x = fmaf(x0, wv.x, acc0.x); acc0.y = fmaf(x0, wv.y, acc0.y);
                acc0.z = fmaf(x0, wv.z, acc0.z); acc0.w = fmaf(x0, wv.w, acc0.w);
                acc1.x = fmaf(x1, wv.x, acc1.x); acc1.y = fmaf(x1, wv.y, acc1.y);
                acc1.z = fmaf(x1, wv.z, acc1.z); acc1.w = fmaf(x1, wv.w, acc1.w);
                acc2.x = fmaf(x2, wv.x, acc2.x); acc2.y = fmaf(x2, wv.y, acc2.y);
                acc2.z = fmaf(x2, wv.z, acc2.z); acc2.w = fmaf(x2, wv.w, acc2.w);
                acc3.x = fmaf(x3, wv.x, acc3.x); acc3.y = fmaf(x3, wv.y, acc3.y);
                acc3.z = fmaf(x3, wv.z, acc3.z); acc3.w = fmaf(x3, wv.w, acc3.w);
            }
        }
        float4 bb = reinterpret_cast<const float4*>(bd)[lane];
        acc0.x += bb.x; acc0.y += bb.y; acc0.z += bb.z; acc0.w += bb.w;
        acc1.x += bb.x; acc1.y += bb.y; acc1.z += bb.z; acc1.w += bb.w;
        acc2.x += bb.x; acc2.y += bb.y; acc2.z += bb.z; acc2.w += bb.w;
        acc3.x += bb.x; acc3.y += bb.y; acc3.z += bb.z; acc3.w += bb.w;
        {
            float4* gdf4 = reinterpret_cast<float4*>(g_df);
            const int r0 = i0 + 4 * w;
            gdf4[(size_t)(r0 + 0) * 32 + lane] = acc0;
            gdf4[(size_t)(r0 + 1) * 32 + lane] = acc1;
            gdf4[(size_t)(r0 + 2) * 32 + lane] = acc2;
            gdf4[(size_t)(r0 + 3) * 32 + lane] = acc3;
        }
    }

    // -------- last block finalizes dmin/invden + atom ranges ------------------
    __threadfence();
    __syncthreads();
    if (t == 0) isLast = (atomicAdd(&g_gemm_done, 1) == NGEMM - 1);
    __syncthreads();
    if (isLast && t < B) {
        float dmin = __int_as_float(__ldcg(&g_smn[t]));
        float dmax = __int_as_float(__ldcg(&g_smx[t]));
        if (!isfinite(dmin)) dmin = 0.0f;
        float den = (dmax > dmin) ? (dmax - dmin) : 1.0f;
        g_dminf[t] = dmin;
        g_invden[t] = 1.0f / den;
        g_as[t] = s_as8[t];
        g_ae[t] = s_ae8[t];
        g_smn[t] = 0x7F800000;   // reset for next graph replay
        g_smx[t] = 0;
        if (t == 0) g_gemm_done = 0;
    }
}

// =================== Kernel B: main streaming write (R3-validated) ===========
__global__ void __launch_bounds__(256) k_main(const int* __restrict__ seg_res,
                                              const float* __restrict__ tpos,
                                              const float* __restrict__ dpos,
                                              float* __restrict__ out) {
    const int i = blockIdx.x;
    const int b = seg_res[i];
    const int as = g_as[b], ae = g_ae[b];

    __shared__ float s_tf[H];
    __shared__ float s_dn[NA];

    if (threadIdx.x < H) s_tf[threadIdx.x] = g_tf[i * H + threadIdx.x];

    const float px = tpos[3 * i], py = tpos[3 * i + 1], pz = tpos[3 * i + 2];
    const float dmin = g_dminf[b], inv = g_invden[b];
    for (int j = as + (int)threadIdx.x; j < ae; j += 256) {
        float dx = px - dpos[3 * j];
        float dy = py - dpos[3 * j + 1];
        float dz = pz - dpos[3 * j + 2];
        s_dn[j - as] = (sqrtf(dx * dx + dy * dy + dz * dz) - dmin) * inv;
    }
    __syncthreads();

    float4* out4 = reinterpret_cast<float4*>(out) + (size_t)i * (NA * H / 4);
    const float4 z4 = make_float4(0.f, 0.f, 0.f, 0.f);

    const int nl = as * (H / 4);
    for (int idx = threadIdx.x; idx < nl; idx += 256) __stcs(&out4[idx], z4);

    const int nr = (NA - ae) * (H / 4);
    float4* outr = out4 + ae * (H / 4);
    for (int idx = threadIdx.x; idx < nr; idx += 256) __stcs(&outr[idx], z4);

    const int nm = (ae - as) * (H / 4);
    const float4* df4 = reinterpret_cast<const float4*>(g_df);
    const float4* tf4 = reinterpret_cast<const float4*>(s_tf);
    float4* outm = out4 + as * (H / 4);
    for (int idx = threadIdx.x; idx < nm; idx += 256) {
        const int jo = idx >> 5;
        const int q  = idx & 31;
        const float dn = s_dn[jo];
        const float4 tv = tf4[q];
        const float4 dv = df4[(size_t)(as + jo) * (H / 4) + q];
        float4 r;
        r.x = tanhf(tv.x - dv.x + dn);
        r.y = tanhf(tv.y - dv.y + dn);
        r.z = tanhf(tv.z - dv.z + dn);
        r.w = tanhf(tv.w - dv.w + dn);
        __stcs(&outm[idx], r);
    }
}

// ---------------- launch -------------------------------------------------------
extern "C" void kernel_launch(void* const* d_in, const int* in_sizes, int n_in,
                              void* d_out, int out_size) {
    const float* target_feature = (const float*)d_in[0];
    const float* drug_feature   = (const float*)d_in[1];
    const float* target_pos     = (const float*)d_in[2];
    const float* drug_pos       = (const float*)d_in[3];
    const float* Wt             = (const float*)d_in[4];
    const float* bt             = (const float*)d_in[5];
    const float* Wd             = (const float*)d_in[6];
    const float* bd             = (const float*)d_in[7];
    const int*   seg_res        = (const int*)d_in[8];
    const int*   seg_atom       = (const int*)d_in[9];
    float* out = (float*)d_out;

    cudaFuncSetAttribute(kA, cudaFuncAttributeMaxDynamicSharedMemorySize, DYN_BYTES);

    kA<<<NGEMM, 256, DYN_BYTES>>>(target_feature, Wt, bt,
                                  drug_feature, Wd, bd,
                                  target_pos, drug_pos,
                                  seg_res, seg_atom);
    k_main<<<NR, 256>>>(seg_res, target_pos, drug_pos, out);
}

// round 13
// speedup vs baseline: 1.0790x; 1.0790x over previous
#include <cuda_runtime.h>
#include <math.h>
#include <stdint.h>

#define NR 3200
#define NA 320
#define TD 512
#define DD 128
#define H  128
#define B  8

#define NTF 134              // tf GEMM blocks, 24 rows each (3 rows/warp)
#define TROWS 24
#define NDF 10               // df GEMM blocks, 32 rows each (4 rows/warp)
#define NGEMM (NTF + NDF)    // 144 <= 148 SMs
#define KT  32               // k-tile for W staging

// dynamic smem for kA: tf: 24*512 A + 32*128 W = 16384 floats = 64 KB
#define DYN_FLOATS (TROWS * TD + KT * H)
#define DYN_BYTES  (DYN_FLOATS * 4)

// ---------------- scratch (device globals) ----------------------------------
__device__ float g_tf[NR * H];
__device__ float g_df[NA * H];
// statically initialized; finalize resets after use (graph replay safe)
__device__ int   g_smn[B] = {0x7F800000,0x7F800000,0x7F800000,0x7F800000,
                             0x7F800000,0x7F800000,0x7F800000,0x7F800000};
__device__ int   g_smx[B] = {0,0,0,0,0,0,0,0};
__device__ float g_dminf[B];
__device__ float g_invden[B];
__device__ int   g_as[B];
__device__ int   g_ae[B];
__device__ int   g_gemm_done = 0;

__device__ __forceinline__ int lowerb(const int* __restrict__ a, int n, int key) {
    int lo = 0, hi = n;
    while (lo < hi) { int m = (lo + hi) >> 1; if (a[m] < key) lo = m + 1; else hi = m; }
    return lo;
}

// =================== Kernel A: GEMMs + segment min/max (side stream) =========
__global__ void __launch_bounds__(256)
kA(const float* __restrict__ tfeat,
   const float* __restrict__ Wt,
   const float* __restrict__ bt,
   const float* __restrict__ dfeat,
   const float* __restrict__ Wd,
   const float* __restrict__ bd,
   const float* __restrict__ tpos,
   const float* __restrict__ dpos,
   const int* __restrict__ seg_res,
   const int* __restrict__ seg_atom) {
    extern __shared__ float buf[];
    __shared__ int  s_as8[B], s_ae8[B];
    __shared__ int  s_bmn[B], s_bmx[B];
    __shared__ bool isLast;

    const int t = threadIdx.x;
    const int w = t >> 5, lane = t & 31;
    const int bid = blockIdx.x;

    if (t < B) {
        s_as8[t] = lowerb(seg_atom, NA, t);
        s_ae8[t] = lowerb(seg_atom, NA, t + 1);
        s_bmn[t] = 0x7F800000;
        s_bmx[t] = 0;
    }
    __syncthreads();

    if (bid < NTF) {
        // ---- tf GEMM: 24 rows, 3 rows/warp, Wt k-tiled (KT=32) in smem ----
        float* sA = buf;                                            // 24*512 floats
        float4* sW4 = reinterpret_cast<float4*>(buf + TROWS * TD);  // 32*128 floats

        const int i0 = bid * TROWS;
        {
            float4* dst = reinterpret_cast<float4*>(sA);
            const float4 z = make_float4(0.f, 0.f, 0.f, 0.f);
            #pragma unroll
            for (int idx = t; idx < TROWS * TD / 4; idx += 256) {
                const int row = i0 + idx / (TD / 4);
                dst[idx] = (row < NR)
                    ? reinterpret_cast<const float4*>(tfeat)[(size_t)i0 * (TD / 4) + idx]
                    : z;
            }
        }

        const float* a0 = sA + (3 * w) * TD;
        const float* a1 = sA + (3 * w + 1) * TD;
        const float* a2 = sA + (3 * w + 2) * TD;
        const float4* W4 = reinterpret_cast<const float4*>(Wt);
        float4 acc0 = make_float4(0.f, 0.f, 0.f, 0.f);
        float4 acc1 = make_float4(0.f, 0.f, 0.f, 0.f);
        float4 acc2 = make_float4(0.f, 0.f, 0.f, 0.f);

        for (int kt = 0; kt < TD; kt += KT) {
            __syncthreads();
            #pragma unroll
            for (int idx = t; idx < KT * H / 4; idx += 256)
                sW4[idx] = W4[(size_t)kt * (H / 4) + idx];
            __syncthreads();
            #pragma unroll 8
            for (int k = 0; k < KT; k++) {
                float4 wv = sW4[k * 32 + lane];
                float x0 = a0[kt + k], x1 = a1[kt + k], x2 = a2[kt + k];
                acc0.x = fmaf(x0, wv.x, acc0.x); acc0.y = fmaf(x0, wv.y, acc0.y);
                acc0.z = fmaf(x0, wv.z, acc0.z); acc0.w = fmaf(x0, wv.w, acc0.w);
                acc1.x = fmaf(x1, wv.x, acc1.x); acc1.y = fmaf(x1, wv.y, acc1.y);
                acc1.z = fmaf(x1, wv.z, acc1.z); acc1.w = fmaf(x1, wv.w, acc1.w);
                acc2.x = fmaf(x2, wv.x, acc2.x); acc2.y = fmaf(x2, wv.y, acc2.y);
                acc2.z = fmaf(x2, wv.z, acc2.z); acc2.w = fmaf(x2, wv.w, acc2.w);
            }
        }
        float4 bb = reinterpret_cast<const float4*>(bt)[lane];
        acc0.x += bb.x; acc0.y += bb.y; acc0.z += bb.z; acc0.w += bb.w;
        acc1.x += bb.x; acc1.y += bb.y; acc1.z += bb.z; acc1.w += bb.w;
        acc2.x += bb.x; acc2.y += bb.y; acc2.z += bb.z; acc2.w += bb.w;
        {
            const int r0 = i0 + 3 * w;
            float4* gtf4 = reinterpret_cast<float4*>(g_tf);
            if (r0 + 0 < NR) gtf4[(size_t)(r0 + 0) * 32 + lane] = acc0;
            if (r0 + 1 < NR) gtf4[(size_t)(r0 + 1) * 32 + lane] = acc1;
            if (r0 + 2 < NR) gtf4[(size_t)(r0 + 2) * 32 + lane] = acc2;
        }

        // ---- per-row distance min/max -> smem seg reduce -> global atomics --
        #pragma unroll
        for (int r2 = 0; r2 < 3; r2++) {
            const int i = i0 + 3 * w + r2;
            if (i >= NR) break;
            const int b = seg_res[i];
            const int as = s_as8[b], ae = s_ae8[b];
            const float px = tpos[3 * i], py = tpos[3 * i + 1], pz = tpos[3 * i + 2];
            float mn = INFINITY, mx = 0.0f;
            for (int j = as + lane; j < ae; j += 32) {
                float dx = px - dpos[3 * j];
                float dy = py - dpos[3 * j + 1];
                float dz = pz - dpos[3 * j + 2];
                float d = sqrtf(dx * dx + dy * dy + dz * dz);
                mn = fminf(mn, d); mx = fmaxf(mx, d);
            }
            #pragma unroll
            for (int o = 16; o; o >>= 1) {
                mn = fminf(mn, __shfl_xor_sync(0xFFFFFFFFu, mn, o));
                mx = fmaxf(mx, __shfl_xor_sync(0xFFFFFFFFu, mx, o));
            }
            if (lane == 0) {
                atomicMin(&s_bmn[b], __float_as_int(mn));  // nonneg: int cmp == float cmp
                atomicMax(&s_bmx[b], __float_as_int(mx));
            }
        }
        __syncthreads();
        if (t < B) {
            if (s_bmn[t] != 0x7F800000) atomicMin(&g_smn[t], s_bmn[t]);
            if (s_bmx[t] != 0)          atomicMax(&g_smx[t], s_bmx[t]);
        }
    } else {
        // ---- df GEMM: 32 rows, 4 rows/warp, Wd k-tiled (KT=32) in smem ----
        float* sA = buf;                                          // 32*128 floats
        float4* sW4 = reinterpret_cast<float4*>(buf + 32 * DD);   // 32*128 floats

        const int i0 = (bid - NTF) * 32;
        {
            const float4* src = reinterpret_cast<const float4*>(dfeat + (size_t)i0 * DD);
            float4* dst = reinterpret_cast<float4*>(sA);
            #pragma unroll
            for (int idx = t; idx < 32 * DD / 4; idx += 256) dst[idx] = src[idx];
        }

        const float* a0 = sA + (4 * w) * DD;
        const float* a1 = sA + (4 * w + 1) * DD;
        const float* a2 = sA + (4 * w + 2) * DD;
        const float* a3 = sA + (4 * w + 3) * DD;
        const float4* W4 = reinterpret_cast<const float4*>(Wd);
        float4 acc0 = make_float4(0.f, 0.f, 0.f, 0.f);
        float4 acc1 = make_float4(0.f, 0.f, 0.f, 0.f);
        float4 acc2 = make_float4(0.f, 0.f, 0.f, 0.f);
        float4 acc3 = make_float4(0.f, 0.f, 0.f, 0.f);

        for (int kt = 0; kt < DD; kt += KT) {
            __syncthreads();
            #pragma unroll
            for (int idx = t; idx < KT * H / 4; idx += 256)
                sW4[idx] = W4[(size_t)kt * (H / 4) + idx];
            __syncthreads();
            #pragma unroll 8
            for (int k = 0; k < KT; k++) {
                float4 wv = sW4[k * 32 + lane];
                float x0 = a0[kt + k], x1 = a1[kt + k], x2 = a2[kt + k], x3 = a3[kt + k];
                acc0.x = fmaf(x0, wv.x, acc0.x); acc0.y = fmaf(x0, wv.y, acc0.y);
                acc0.z = fmaf(x0, wv.z, acc0.z); acc0.w = fmaf(x0, wv.w, acc0.w);
                acc1.x = fmaf(x1, wv.x, acc1.x); acc1.y = fmaf(x1, wv.y, acc1.y);
                acc1.z = fmaf(x1, wv.z, acc1.z); acc1.w = fmaf(x1, wv.w, acc1.w);
                acc2.x = fmaf(x2, wv.x, acc2.x); acc2.y = fmaf(x2, wv.y, acc2.y);
                acc2.z = fmaf(x2, wv.z, acc2.z); acc2.w = fmaf(x2, wv.w, acc2.w);
                acc3.x = fmaf(x3, wv.x, acc3.x); acc3.y = fmaf(x3, wv.y, acc3.y);
                acc3.z = fmaf(x3, wv.z, acc3.z); acc3.w = fmaf(x3, wv.w, acc3.w);
            }
        }
        float4 bb = reinterpret_cast<const float4*>(bd)[lane];
        acc0.x += bb.x; acc0.y += bb.y; acc0.z += bb.z; acc0.w += bb.w;
        acc1.x += bb.x; acc1.y += bb.y; acc1.z += bb.z; acc1.w += bb.w;
        acc2.x += bb.x; acc2.y += bb.y; acc2.z += bb.z; acc2.w += bb.w;
        acc3.x += bb.x; acc3.y += bb.y; acc3.z += bb.z; acc3.w += bb.w;
        {
            float4* gdf4 = reinterpret_cast<float4*>(g_df);
            const int r0 = i0 + 4 * w;
            gdf4[(size_t)(r0 + 0) * 32 + lane] = acc0;
            gdf4[(size_t)(r0 + 1) * 32 + lane] = acc1;
            gdf4[(size_t)(r0 + 2) * 32 + lane] = acc2;
            gdf4[(size_t)(r0 + 3) * 32 + lane] = acc3;
        }
    }

    // -------- last block finalizes dmin/invden + atom ranges ------------------
    __threadfence();
    __syncthreads();
    if (t == 0) isLast = (atomicAdd(&g_gemm_done, 1) == NGEMM - 1);
    __syncthreads();
    if (isLast && t < B) {
        float dmin = __int_as_float(__ldcg(&g_smn[t]));
        float dmax = __int_as_float(__ldcg(&g_smx[t]));
        if (!isfinite(dmin)) dmin = 0.0f;
        float den = (dmax > dmin) ? (dmax - dmin) : 1.0f;
        g_dminf[t] = dmin;
        g_invden[t] = 1.0f / den;
        g_as[t] = s_as8[t];
        g_ae[t] = s_ae8[t];
        g_smn[t] = 0x7F800000;   // reset for next graph replay
        g_smx[t] = 0;
        if (t == 0) g_gemm_done = 0;
    }
}

// =================== Kernel Z: zero stripes (independent of kA) ==============
__global__ void __launch_bounds__(256) k_zero(const int* __restrict__ seg_res,
                                              const int* __restrict__ seg_atom,
                                              float* __restrict__ out) {
    __shared__ int s_as, s_ae;
    const int i = blockIdx.x;
    if (threadIdx.x == 0) {
        const int b = seg_res[i];
        s_as = lowerb(seg_atom, NA, b);
        s_ae = lowerb(seg_atom, NA, b + 1);
    }
    __syncthreads();
    const int as = s_as, ae = s_ae;

    float4* out4 = reinterpret_cast<float4*>(out) + (size_t)i * (NA * H / 4);
    const float4 z4 = make_float4(0.f, 0.f, 0.f, 0.f);

    const int nl = as * (H / 4);
    for (int idx = threadIdx.x; idx < nl; idx += 256) __stcs(&out4[idx], z4);

    const int nr = (NA - ae) * (H / 4);
    float4* outr = out4 + ae * (H / 4);
    for (int idx = threadIdx.x; idx < nr; idx += 256) __stcs(&outr[idx], z4);
}

// =================== Kernel T: tanh middles (joins kA + k_zero) ==============
__global__ void __launch_bounds__(256) k_tanh(const int* __restrict__ seg_res,
                                              const float* __restrict__ tpos,
                                              const float* __restrict__ dpos,
                                              float* __restrict__ out) {
    const int i = blockIdx.x;
    const int b = seg_res[i];
    const int as = g_as[b], ae = g_ae[b];
    const int na = ae - as;
    if (na <= 0) return;

    __shared__ float s_tf[H];
    __shared__ float s_dn[NA];

    if (threadIdx.x < H) s_tf[threadIdx.x] = g_tf[i * H + threadIdx.x];

    const float px = tpos[3 * i], py = tpos[3 * i + 1], pz = tpos[3 * i + 2];
    const float dmin = g_dminf[b], inv = g_invden[b];
    for (int j = as + (int)threadIdx.x; j < ae; j += 256) {
        float dx = px - dpos[3 * j];
        float dy = py - dpos[3 * j + 1];
        float dz = pz - dpos[3 * j + 2];
        s_dn[j - as] = (sqrtf(dx * dx + dy * dy + dz * dz) - dmin) * inv;
    }
    __syncthreads();

    float4* outm = reinterpret_cast<float4*>(out) + (size_t)i * (NA * H / 4) + as * (H / 4);
    const float4* df4 = reinterpret_cast<const float4*>(g_df);
    const float4* tf4 = reinterpret_cast<const float4*>(s_tf);
    const int nm = na * (H / 4);
    for (int idx = threadIdx.x; idx < nm; idx += 256) {
        const int jo = idx >> 5;
        const int q  = idx & 31;
        const float dn = s_dn[jo];
        const float4 tv = tf4[q];
        const float4 dv = df4[(size_t)(as + jo) * 32 + q];
        float4 r;
        r.x = tanhf(tv.x - dv.x + dn);
        r.y = tanhf(tv.y - dv.y + dn);
        r.z = tanhf(tv.z - dv.z + dn);
        r.w = tanhf(tv.w - dv.w + dn);
        __stcs(&outm[idx], r);
    }
}

// ---------------- launch: forked graph (kA || k_zero) -> k_tanh ---------------
extern "C" void kernel_launch(void* const* d_in, const int* in_sizes, int n_in,
                              void* d_out, int out_size) {
    const float* target_feature = (const float*)d_in[0];
    const float* drug_feature   = (const float*)d_in[1];
    const float* target_pos     = (const float*)d_in[2];
    const float* drug_pos       = (const float*)d_in[3];
    const float* Wt             = (const float*)d_in[4];
    const float* bt             = (const float*)d_in[5];
    const float* Wd             = (const float*)d_in[6];
    const float* bd             = (const float*)d_in[7];
    const int*   seg_res        = (const int*)d_in[8];
    const int*   seg_atom       = (const int*)d_in[9];
    float* out = (float*)d_out;

    static cudaStream_t s_side = nullptr;
    static cudaEvent_t  e_fork = nullptr, e_join = nullptr;
    if (s_side == nullptr) {
        cudaStreamCreateWithFlags(&s_side, cudaStreamNonBlocking);
        cudaEventCreateWithFlags(&e_fork, cudaEventDisableTiming);
        cudaEventCreateWithFlags(&e_join, cudaEventDisableTiming);
        cudaFuncSetAttribute(kA, cudaFuncAttributeMaxDynamicSharedMemorySize, DYN_BYTES);
    }

    // fork: side stream runs kA concurrently with k_zero on the main stream
    cudaEventRecord(e_fork, 0);
    cudaStreamWaitEvent(s_side, e_fork, 0);
    kA<<<NGEMM, 256, DYN_BYTES, s_side>>>(target_feature, Wt, bt,
                                          drug_feature, Wd, bd,
                                          target_pos, drug_pos,
                                          seg_res, seg_atom);
    cudaEventRecord(e_join, s_side);

    k_zero<<<NR, 256>>>(seg_res, seg_atom, out);

    // join: k_tanh needs both kA's results and (for output completeness) runs
    // after k_zero by stream order
    cudaStreamWaitEvent(0, e_join, 0);
    k_tanh<<<NR, 256>>>(seg_res, target_pos, drug_pos, out);
}

// round 14
// speedup vs baseline: 1.0945x; 1.0144x over previous
#include <cuda_runtime.h>
#include <math.h>
#include <stdint.h>

#define NR 3200
#define NA 320
#define TD 512
#define DD 128
#define H  128
#define B  8

#define NTF 134              // tf GEMM blocks, 24 rows each (3 rows/warp)
#define TROWS 24
#define NDF 10               // df GEMM blocks, 32 rows each (4 rows/warp)
#define NGEMM (NTF + NDF)    // 144 <= 148 SMs
#define KT  32               // k-tile for W staging

// dynamic smem for kA: tf: 24*512 A + 32*128 W = 16384 floats = 64 KB
#define DYN_FLOATS (TROWS * TD + KT * H)
#define DYN_BYTES  (DYN_FLOATS * 4)

// ---------------- scratch (device globals) ----------------------------------
__device__ float g_tf[NR * H];
__device__ float g_df[NA * H];
// statically initialized; finalize resets after use (graph replay safe)
__device__ int   g_smn[B] = {0x7F800000,0x7F800000,0x7F800000,0x7F800000,
                             0x7F800000,0x7F800000,0x7F800000,0x7F800000};
__device__ int   g_smx[B] = {0,0,0,0,0,0,0,0};
__device__ float g_dminf[B];
__device__ float g_invden[B];
__device__ int   g_as[B];
__device__ int   g_ae[B];
__device__ int   g_gemm_done = 0;

__device__ __forceinline__ int lowerb(const int* __restrict__ a, int n, int key) {
    int lo = 0, hi = n;
    while (lo < hi) { int m = (lo + hi) >> 1; if (a[m] < key) lo = m + 1; else hi = m; }
    return lo;
}

// =================== Kernel A: GEMMs + segment min/max (side stream) =========
__global__ void __launch_bounds__(256)
kA(const float* __restrict__ tfeat,
   const float* __restrict__ Wt,
   const float* __restrict__ bt,
   const float* __restrict__ dfeat,
   const float* __restrict__ Wd,
   const float* __restrict__ bd,
   const float* __restrict__ tpos,
   const float* __restrict__ dpos,
   const int* __restrict__ seg_res,
   const int* __restrict__ seg_atom) {
    extern __shared__ float buf[];
    __shared__ int  s_as8[B], s_ae8[B];
    __shared__ int  s_bmn[B], s_bmx[B];
    __shared__ bool isLast;

    const int t = threadIdx.x;
    const int w = t >> 5, lane = t & 31;
    const int bid = blockIdx.x;

    if (t < B) {
        s_as8[t] = lowerb(seg_atom, NA, t);
        s_ae8[t] = lowerb(seg_atom, NA, t + 1);
        s_bmn[t] = 0x7F800000;
        s_bmx[t] = 0;
    }
    __syncthreads();

    if (bid < NTF) {
        // ---- tf GEMM: 24 rows, 3 rows/warp, Wt k-tiled (KT=32) in smem ----
        float* sA = buf;                                            // 24*512 floats
        float4* sW4 = reinterpret_cast<float4*>(buf + TROWS * TD);  // 32*128 floats

        const int i0 = bid * TROWS;
        {
            float4* dst = reinterpret_cast<float4*>(sA);
            const float4 z = make_float4(0.f, 0.f, 0.f, 0.f);
            #pragma unroll
            for (int idx = t; idx < TROWS * TD / 4; idx += 256) {
                const int row = i0 + idx / (TD / 4);
                dst[idx] = (row < NR)
                    ? reinterpret_cast<const float4*>(tfeat)[(size_t)i0 * (TD / 4) + idx]
                    : z;
            }
        }

        const float* a0 = sA + (3 * w) * TD;
        const float* a1 = sA + (3 * w + 1) * TD;
        const float* a2 = sA + (3 * w + 2) * TD;
        const float4* W4 = reinterpret_cast<const float4*>(Wt);
        float4 acc0 = make_float4(0.f, 0.f, 0.f, 0.f);
        float4 acc1 = make_float4(0.f, 0.f, 0.f, 0.f);
        float4 acc2 = make_float4(0.f, 0.f, 0.f, 0.f);

        for (int kt = 0; kt < TD; kt += KT) {
            __syncthreads();
            #pragma unroll
            for (int idx = t; idx < KT * H / 4; idx += 256)
                sW4[idx] = W4[(size_t)kt * (H / 4) + idx];
            __syncthreads();
            #pragma unroll 8
            for (int k = 0; k < KT; k++) {
                float4 wv = sW4[k * 32 + lane];
                float x0 = a0[kt + k], x1 = a1[kt + k], x2 = a2[kt + k];
                acc0.x = fmaf(x0, wv.x, acc0.x); acc0.y = fmaf(x0, wv.y, acc0.y);
                acc0.z = fmaf(x0, wv.z, acc0.z); acc0.w = fmaf(x0, wv.w, acc0.w);
                acc1.x = fmaf(x1, wv.x, acc1.x); acc1.y = fmaf(x1, wv.y, acc1.y);
                acc1.z = fmaf(x1, wv.z, acc1.z); acc1.w = fmaf(x1, wv.w, acc1.w);
                acc2.x = fmaf(x2, wv.x, acc2.x); acc2.y = fmaf(x2, wv.y, acc2.y);
                acc2.z = fmaf(x2, wv.z, acc2.z); acc2.w = fmaf(x2, wv.w, acc2.w);
            }
        }
        float4 bb = reinterpret_cast<const float4*>(bt)[lane];
        acc0.x += bb.x; acc0.y += bb.y; acc0.z += bb.z; acc0.w += bb.w;
        acc1.x += bb.x; acc1.y += bb.y; acc1.z += bb.z; acc1.w += bb.w;
        acc2.x += bb.x; acc2.y += bb.y; acc2.z += bb.z; acc2.w += bb.w;
        {
            const int r0 = i0 + 3 * w;
            float4* gtf4 = reinterpret_cast<float4*>(g_tf);
            if (r0 + 0 < NR) gtf4[(size_t)(r0 + 0) * 32 + lane] = acc0;
            if (r0 + 1 < NR) gtf4[(size_t)(r0 + 1) * 32 + lane] = acc1;
            if (r0 + 2 < NR) gtf4[(size_t)(r0 + 2) * 32 + lane] = acc2;
        }

        // ---- per-row distance min/max -> smem seg reduce -> global atomics --
        #pragma unroll
        for (int r2 = 0; r2 < 3; r2++) {
            const int i = i0 + 3 * w + r2;
            if (i >= NR) break;
            const int b = seg_res[i];
            const int as = s_as8[b], ae = s_ae8[b];
            const float px = tpos[3 * i], py = tpos[3 * i + 1], pz = tpos[3 * i + 2];
            float mn = INFINITY, mx = 0.0f;
            for (int j = as + lane; j < ae; j += 32) {
                float dx = px - dpos[3 * j];
                float dy = py - dpos[3 * j + 1];
                float dz = pz - dpos[3 * j + 2];
                float d = sqrtf(dx * dx + dy * dy + dz * dz);
                mn = fminf(mn, d); mx = fmaxf(mx, d);
            }
            #pragma unroll
            for (int o = 16; o; o >>= 1) {
                mn = fminf(mn, __shfl_xor_sync(0xFFFFFFFFu, mn, o));
                mx = fmaxf(mx, __shfl_xor_sync(0xFFFFFFFFu, mx, o));
            }
            if (lane == 0) {
                atomicMin(&s_bmn[b], __float_as_int(mn));  // nonneg: int cmp == float cmp
                atomicMax(&s_bmx[b], __float_as_int(mx));
            }
        }
        __syncthreads();
        if (t < B) {
            if (s_bmn[t] != 0x7F800000) atomicMin(&g_smn[t], s_bmn[t]);
            if (s_bmx[t] != 0)          atomicMax(&g_smx[t], s_bmx[t]);
        }
    } else {
        // ---- df GEMM: 32 rows, 4 rows/warp, Wd k-tiled (KT=32) in smem ----
        float* sA = buf;                                          // 32*128 floats
        float4* sW4 = reinterpret_cast<float4*>(buf + 32 * DD);   // 32*128 floats

        const int i0 = (bid - NTF) * 32;
        {
            const float4* src = reinterpret_cast<const float4*>(dfeat + (size_t)i0 * DD);
            float4* dst = reinterpret_cast<float4*>(sA);
            #pragma unroll
            for (int idx = t; idx < 32 * DD / 4; idx += 256) dst[idx] = src[idx];
        }

        const float* a0 = sA + (4 * w) * DD;
        const float* a1 = sA + (4 * w + 1) * DD;
        const float* a2 = sA + (4 * w + 2) * DD;
        const float* a3 = sA + (4 * w + 3) * DD;
        const float4* W4 = reinterpret_cast<const float4*>(Wd);
        float4 acc0 = make_float4(0.f, 0.f, 0.f, 0.f);
        float4 acc1 = make_float4(0.f, 0.f, 0.f, 0.f);
        float4 acc2 = make_float4(0.f, 0.f, 0.f, 0.f);
        float4 acc3 = make_float4(0.f, 0.f, 0.f, 0.f);

        for (int kt = 0; kt < DD; kt += KT) {
            __syncthreads();
            #pragma unroll
            for (int idx = t; idx < KT * H / 4; idx += 256)
                sW4[idx] = W4[(size_t)kt * (H / 4) + idx];
            __syncthreads();
            #pragma unroll 8
            for (int k = 0; k < KT; k++) {
                float4 wv = sW4[k * 32 + lane];
                float x0 = a0[kt + k], x1 = a1[kt + k], x2 = a2[kt + k], x3 = a3[kt + k];
                acc0.x = fmaf(x0, wv.x, acc0.x); acc0.y = fmaf(x0, wv.y, acc0.y);
                acc0.z = fmaf(x0, wv.z, acc0.z); acc0.w = fmaf(x0, wv.w, acc0.w);
                acc1.x = fmaf(x1, wv.x, acc1.x); acc1.y = fmaf(x1, wv.y, acc1.y);
                acc1.z = fmaf(x1, wv.z, acc1.z); acc1.w = fmaf(x1, wv.w, acc1.w);
                acc2.x = fmaf(x2, wv.x, acc2.x); acc2.y = fmaf(x2, wv.y, acc2.y);
                acc2.z = fmaf(x2, wv.z, acc2.z); acc2.w = fmaf(x2, wv.w, acc2.w);
                acc3.x = fmaf(x3, wv.x, acc3.x); acc3.y = fmaf(x3, wv.y, acc3.y);
                acc3.z = fmaf(x3, wv.z, acc3.z); acc3.w = fmaf(x3, wv.w, acc3.w);
            }
        }
        float4 bb = reinterpret_cast<const float4*>(bd)[lane];
        acc0.x += bb.x; acc0.y += bb.y; acc0.z += bb.z; acc0.w += bb.w;
        acc1.x += bb.x; acc1.y += bb.y; acc1.z += bb.z; acc1.w += bb.w;
        acc2.x += bb.x; acc2.y += bb.y; acc2.z += bb.z; acc2.w += bb.w;
        acc3.x += bb.x; acc3.y += bb.y; acc3.z += bb.z; acc3.w += bb.w;
        {
            float4* gdf4 = reinterpret_cast<float4*>(g_df);
            const int r0 = i0 + 4 * w;
            gdf4[(size_t)(r0 + 0) * 32 + lane] = acc0;
            gdf4[(size_t)(r0 + 1) * 32 + lane] = acc1;
            gdf4[(size_t)(r0 + 2) * 32 + lane] = acc2;
            gdf4[(size_t)(r0 + 3) * 32 + lane] = acc3;
        }
    }

    // -------- last block finalizes dmin/invden + atom ranges ------------------
    __threadfence();
    __syncthreads();
    if (t == 0) isLast = (atomicAdd(&g_gemm_done, 1) == NGEMM - 1);
    __syncthreads();
    if (isLast && t < B) {
        float dmin = __int_as_float(__ldcg(&g_smn[t]));
        float dmax = __int_as_float(__ldcg(&g_smx[t]));
        if (!isfinite(dmin)) dmin = 0.0f;
        float den = (dmax > dmin) ? (dmax - dmin) : 1.0f;
        g_dminf[t] = dmin;
        g_invden[t] = 1.0f / den;
        g_as[t] = s_as8[t];
        g_ae[t] = s_ae8[t];
        g_smn[t] = 0x7F800000;   // reset for next graph replay
        g_smx[t] = 0;
        if (t == 0) g_gemm_done = 0;
    }
}

// =================== Kernel Z: zero stripes (independent of kA) ==============
__global__ void __launch_bounds__(256) k_zero(const int* __restrict__ seg_res,
                                              const int* __restrict__ seg_atom,
                                              float* __restrict__ out) {
    __shared__ int s_as, s_ae;
    const int i = blockIdx.x;
    if (threadIdx.x == 0) {
        const int b = seg_res[i];
        s_as = lowerb(seg_atom, NA, b);
        s_ae = lowerb(seg_atom, NA, b + 1);
    }
    __syncthreads();
    const int as = s_as, ae = s_ae;

    float4* out4 = reinterpret_cast<float4*>(out) + (size_t)i * (NA * H / 4);
    const float4 z4 = make_float4(0.f, 0.f, 0.f, 0.f);

    const int nl = as * (H / 4);
    for (int idx = threadIdx.x; idx < nl; idx += 256) __stcs(&out4[idx], z4);

    const int nr = (NA - ae) * (H / 4);
    float4* outr = out4 + ae * (H / 4);
    for (int idx = threadIdx.x; idx < nr; idx += 256) __stcs(&outr[idx], z4);
}

// =================== Kernel T: tanh middles (after kA, || k_zero) ============
__global__ void __launch_bounds__(256) k_tanh(const int* __restrict__ seg_res,
                                              const float* __restrict__ tpos,
                                              const float* __restrict__ dpos,
                                              float* __restrict__ out) {
    const int i = blockIdx.x;
    const int b = seg_res[i];
    const int as = g_as[b], ae = g_ae[b];
    const int na = ae - as;
    if (na <= 0) return;

    __shared__ float s_tf[H];
    __shared__ float s_dn[NA];

    if (threadIdx.x < H) s_tf[threadIdx.x] = g_tf[i * H + threadIdx.x];

    const float px = tpos[3 * i], py = tpos[3 * i + 1], pz = tpos[3 * i + 2];
    const float dmin = g_dminf[b], inv = g_invden[b];
    for (int j = as + (int)threadIdx.x; j < ae; j += 256) {
        float dx = px - dpos[3 * j];
        float dy = py - dpos[3 * j + 1];
        float dz = pz - dpos[3 * j + 2];
        s_dn[j - as] = (sqrtf(dx * dx + dy * dy + dz * dz) - dmin) * inv;
    }
    __syncthreads();

    float4* outm = reinterpret_cast<float4*>(out) + (size_t)i * (NA * H / 4) + as * (H / 4);
    const float4* df4 = reinterpret_cast<const float4*>(g_df);
    const float4* tf4 = reinterpret_cast<const float4*>(s_tf);
    const int nm = na * (H / 4);
    for (int idx = threadIdx.x; idx < nm; idx += 256) {
        const int jo = idx >> 5;
        const int q  = idx & 31;
        const float dn = s_dn[jo];
        const float4 tv = tf4[q];
        const float4 dv = df4[(size_t)(as + jo) * 32 + q];
        float4 r;
        r.x = tanhf(tv.x - dv.x + dn);
        r.y = tanhf(tv.y - dv.y + dn);
        r.z = tanhf(tv.z - dv.z + dn);
        r.w = tanhf(tv.w - dv.w + dn);
        __stcs(&outm[idx], r);
    }
}

// ---------------- launch: (kA -> k_tanh) || k_zero, join at end ---------------
extern "C" void kernel_launch(void* const* d_in, const int* in_sizes, int n_in,
                              void* d_out, int out_size) {
    const float* target_feature = (const float*)d_in[0];
    const float* drug_feature   = (const float*)d_in[1];
    const float* target_pos     = (const float*)d_in[2];
    const float* drug_pos       = (const float*)d_in[3];
    const float* Wt             = (const float*)d_in[4];
    const float* bt             = (const float*)d_in[5];
    const float* Wd             = (const float*)d_in[6];
    const float* bd             = (const float*)d_in[7];
    const int*   seg_res        = (const int*)d_in[8];
    const int*   seg_atom       = (const int*)d_in[9];
    float* out = (float*)d_out;

    static cudaStream_t s_side = nullptr;
    static cudaEvent_t  e_fork = nullptr, e_join = nullptr;
    if (s_side == nullptr) {
        cudaStreamCreateWithFlags(&s_side, cudaStreamNonBlocking);
        cudaEventCreateWithFlags(&e_fork, cudaEventDisableTiming);
        cudaEventCreateWithFlags(&e_join, cudaEventDisableTiming);
        cudaFuncSetAttribute(kA, cudaFuncAttributeMaxDynamicSharedMemorySize, DYN_BYTES);
    }

    // fork: side stream runs kA then k_tanh, concurrent with k_zero on main.
    // k_tanh depends only on kA (stream order); its output stripes are
    // disjoint (512B-aligned) from k_zero's stripes.
    cudaEventRecord(e_fork, 0);
    cudaStreamWaitEvent(s_side, e_fork, 0);
    kA<<<NGEMM, 256, DYN_BYTES, s_side>>>(target_feature, Wt, bt,
                                          drug_feature, Wd, bd,
                                          target_pos, drug_pos,
                                          seg_res, seg_atom);
    k_tanh<<<NR, 256, 0, s_side>>>(seg_res, target_pos, drug_pos, out);
    cudaEventRecord(e_join, s_side);

    k_zero<<<NR, 256>>>(seg_res, seg_atom, out);

    // join: graph completes only when both branches are done
    cudaStreamWaitEvent(0, e_join, 0);
}

// round 15
// speedup vs baseline: 1.1093x; 1.0135x over previous
#include <cuda_runtime.h>
#include <math.h>
#include <stdint.h>

#define NR 3200
#define NA 320
#define TD 512
#define DD 128
#define H  128
#define B  8

#define NTF 200              // tf GEMM blocks, 16 rows each (2 rows/warp)
#define NDF 10               // df GEMM blocks, 32 rows each (4 rows/warp)
#define NGEMM (NTF + NDF)
#define KT  32               // k-tile for W staging

// dynamic smem for kA: tf: 16*512 A + 32*128 W = 12288 floats = 48 KB
#define DYN_FLOATS (16 * TD + KT * H)
#define DYN_BYTES  (DYN_FLOATS * 4)

// ---------------- scratch (device globals) ----------------------------------
__device__ float g_tf[NR * H];
__device__ float g_df[NA * H];
// statically initialized; finalize resets after use (graph replay safe)
__device__ int   g_smn[B] = {0x7F800000,0x7F800000,0x7F800000,0x7F800000,
                             0x7F800000,0x7F800000,0x7F800000,0x7F800000};
__device__ int   g_smx[B] = {0,0,0,0,0,0,0,0};
__device__ float g_dminf[B];
__device__ float g_invden[B];
__device__ int   g_as[B];
__device__ int   g_ae[B];
__device__ int   g_gemm_done = 0;

__device__ __forceinline__ int lowerb(const int* __restrict__ a, int n, int key) {
    int lo = 0, hi = n;
    while (lo < hi) { int m = (lo + hi) >> 1; if (a[m] < key) lo = m + 1; else hi = m; }
    return lo;
}

// =================== Kernel A: GEMMs + segment min/max (side stream) =========
__global__ void __launch_bounds__(256, 2)
kA(const float* __restrict__ tfeat,
   const float* __restrict__ Wt,
   const float* __restrict__ bt,
   const float* __restrict__ dfeat,
   const float* __restrict__ Wd,
   const float* __restrict__ bd,
   const float* __restrict__ tpos,
   const float* __restrict__ dpos,
   const int* __restrict__ seg_res,
   const int* __restrict__ seg_atom) {
    extern __shared__ float buf[];
    __shared__ int  s_as8[B], s_ae8[B];
    __shared__ int  s_bmn[B], s_bmx[B];
    __shared__ bool isLast;

    const int t = threadIdx.x;
    const int w = t >> 5, lane = t & 31;
    const int bid = blockIdx.x;

    if (t < B) {
        s_as8[t] = lowerb(seg_atom, NA, t);
        s_ae8[t] = lowerb(seg_atom, NA, t + 1);
        s_bmn[t] = 0x7F800000;
        s_bmx[t] = 0;
    }
    __syncthreads();

    if (bid < NTF) {
        // ---- tf GEMM: 16 rows, 2 rows/warp, Wt k-tiled (KT=32) in smem ----
        float* sA = buf;                                         // 16*512 floats
        float4* sW4 = reinterpret_cast<float4*>(buf + 16 * TD);  // 32*128 floats

        const int i0 = bid * 16;
        {
            const float4* src = reinterpret_cast<const float4*>(tfeat + (size_t)i0 * TD);
            float4* dst = reinterpret_cast<float4*>(sA);
            #pragma unroll
            for (int idx = t; idx < 16 * TD / 4; idx += 256) dst[idx] = src[idx];
        }

        const float* a0 = sA + (2 * w) * TD;
        const float* a1 = sA + (2 * w + 1) * TD;
        const float4* W4 = reinterpret_cast<const float4*>(Wt);
        float4 acc0 = make_float4(0.f, 0.f, 0.f, 0.f);
        float4 acc1 = make_float4(0.f, 0.f, 0.f, 0.f);

        for (int kt = 0; kt < TD; kt += KT) {
            __syncthreads();
            #pragma unroll
            for (int idx = t; idx < KT * H / 4; idx += 256)
                sW4[idx] = W4[(size_t)kt * (H / 4) + idx];
            __syncthreads();
            #pragma unroll 8
            for (int k = 0; k < KT; k++) {
                float4 wv = sW4[k * 32 + lane];
                float x0 = a0[kt + k], x1 = a1[kt + k];
                acc0.x = fmaf(x0, wv.x, acc0.x); acc0.y = fmaf(x0, wv.y, acc0.y);
                acc0.z = fmaf(x0, wv.z, acc0.z); acc0.w = fmaf(x0, wv.w, acc0.w);
                acc1.x = fmaf(x1, wv.x, acc1.x); acc1.y = fmaf(x1, wv.y, acc1.y);
                acc1.z = fmaf(x1, wv.z, acc1.z); acc1.w = fmaf(x1, wv.w, acc1.w);
            }
        }
        float4 bb = reinterpret_cast<const float4*>(bt)[lane];
        acc0.x += bb.x; acc0.y += bb.y; acc0.z += bb.z; acc0.w += bb.w;
        acc1.x += bb.x; acc1.y += bb.y; acc1.z += bb.z; acc1.w += bb.w;
        reinterpret_cast<float4*>(g_tf)[(size_t)(i0 + 2 * w) * 32 + lane] = acc0;
        reinterpret_cast<float4*>(g_tf)[(size_t)(i0 + 2 * w + 1) * 32 + lane] = acc1;

        // ---- per-row distance min/max -> smem seg reduce -> global atomics --
        #pragma unroll
        for (int r2 = 0; r2 < 2; r2++) {
            const int i = i0 + 2 * w + r2;
            const int b = seg_res[i];
            const int as = s_as8[b], ae = s_ae8[b];
            const float px = tpos[3 * i], py = tpos[3 * i + 1], pz = tpos[3 * i + 2];
            float mn = INFINITY, mx = 0.0f;
            for (int j = as + lane; j < ae; j += 32) {
                float dx = px - dpos[3 * j];
                float dy = py - dpos[3 * j + 1];
                float dz = pz - dpos[3 * j + 2];
                float d = sqrtf(dx * dx + dy * dy + dz * dz);
                mn = fminf(mn, d); mx = fmaxf(mx, d);
            }
            #pragma unroll
            for (int o = 16; o; o >>= 1) {
                mn = fminf(mn, __shfl_xor_sync(0xFFFFFFFFu, mn, o));
                mx = fmaxf(mx, __shfl_xor_sync(0xFFFFFFFFu, mx, o));
            }
            if (lane == 0) {
                atomicMin(&s_bmn[b], __float_as_int(mn));  // nonneg: int cmp == float cmp
                atomicMax(&s_bmx[b], __float_as_int(mx));
            }
        }
        __syncthreads();
        if (t < B) {
            if (s_bmn[t] != 0x7F800000) atomicMin(&g_smn[t], s_bmn[t]);
            if (s_bmx[t] != 0)          atomicMax(&g_smx[t], s_bmx[t]);
        }
    } else {
        // ---- df GEMM: 32 rows, 4 rows/warp, Wd k-tiled (KT=32) in smem ----
        float* sA = buf;                                          // 32*128 floats
        float4* sW4 = reinterpret_cast<float4*>(buf + 32 * DD);   // 32*128 floats

        const int i0 = (bid - NTF) * 32;
        {
            const float4* src = reinterpret_cast<const float4*>(dfeat + (size_t)i0 * DD);
            float4* dst = reinterpret_cast<float4*>(sA);
            #pragma unroll
            for (int idx = t; idx < 32 * DD / 4; idx += 256) dst[idx] = src[idx];
        }

        const float* a0 = sA + (4 * w) * DD;
        const float* a1 = sA + (4 * w + 1) * DD;
        const float* a2 = sA + (4 * w + 2) * DD;
        const float* a3 = sA + (4 * w + 3) * DD;
        const float4* W4 = reinterpret_cast<const float4*>(Wd);
        float4 acc0 = make_float4(0.f, 0.f, 0.f, 0.f);
        float4 acc1 = make_float4(0.f, 0.f, 0.f, 0.f);
        float4 acc2 = make_float4(0.f, 0.f, 0.f, 0.f);
        float4 acc3 = make_float4(0.f, 0.f, 0.f, 0.f);

        for (int kt = 0; kt < DD; kt += KT) {
            __syncthreads();
            #pragma unroll
            for (int idx = t; idx < KT * H / 4; idx += 256)
                sW4[idx] = W4[(size_t)kt * (H / 4) + idx];
            __syncthreads();
            #pragma unroll 8
            for (int k = 0; k < KT; k++) {
                float4 wv = sW4[k * 32 + lane];
                float x0 = a0[kt + k], x1 = a1[kt + k], x2 = a2[kt + k], x3 = a3[kt + k];
                acc0.x = fmaf(x0, wv.x, acc0.x); acc0.y = fmaf(x0, wv.y, acc0.y);
                acc0.z = fmaf(x0, wv.z, acc0.z); acc0.w = fmaf(x0, wv.w, acc0.w);
                acc1.x = fmaf(x1, wv.x, acc1.x); acc1.y = fmaf(x1, wv.y, acc1.y);
                acc1.z = fmaf(x1, wv.z, acc1.z); acc1.w = fmaf(x1, wv.w, acc1.w);
                acc2.x = fmaf(x2, wv.x, acc2.x); acc2.y = fmaf(x2, wv.y, acc2.y);
                acc2.z = fmaf(x2, wv.z, acc2.z); acc2.w = fmaf(x2, wv.w, acc2.w);
                acc3.x = fmaf(x3, wv.x, acc3.x); acc3.y = fmaf(x3, wv.y, acc3.y);
                acc3.z = fmaf(x3, wv.z, acc3.z); acc3.w = fmaf(x3, wv.w, acc3.w);
            }
        }
        float4 bb = reinterpret_cast<const float4*>(bd)[lane];
        acc0.x += bb.x; acc0.y += bb.y; acc0.z += bb.z; acc0.w += bb.w;
        acc1.x += bb.x; acc1.y += bb.y; acc1.z += bb.z; acc1.w += bb.w;
        acc2.x += bb.x; acc2.y += bb.y; acc2.z += bb.z; acc2.w += bb.w;
        acc3.x += bb.x; acc3.y += bb.y; acc3.z += bb.z; acc3.w += bb.w;
        {
            float4* gdf4 = reinterpret_cast<float4*>(g_df);
            const int r0 = i0 + 4 * w;
            gdf4[(size_t)(r0 + 0) * 32 + lane] = acc0;
            gdf4[(size_t)(r0 + 1) * 32 + lane] = acc1;
            gdf4[(size_t)(r0 + 2) * 32 + lane] = acc2;
            gdf4[(size_t)(r0 + 3) * 32 + lane] = acc3;
        }
    }

    // -------- last block finalizes dmin/invden + atom ranges ------------------
    __threadfence();
    __syncthreads();
    if (t == 0) isLast = (atomicAdd(&g_gemm_done, 1) == NGEMM - 1);
    __syncthreads();
    if (isLast && t < B) {
        float dmin = __int_as_float(__ldcg(&g_smn[t]));
        float dmax = __int_as_float(__ldcg(&g_smx[t]));
        if (!isfinite(dmin)) dmin = 0.0f;
        float den = (dmax > dmin) ? (dmax - dmin) : 1.0f;
        g_dminf[t] = dmin;
        g_invden[t] = 1.0f / den;
        g_as[t] = s_as8[t];
        g_ae[t] = s_ae8[t];
        g_smn[t] = 0x7F800000;   // reset for next graph replay
        g_smx[t] = 0;
        if (t == 0) g_gemm_done = 0;
    }
}

// =================== Kernel Z: zero stripes, 2 rows/block ====================
__global__ void __launch_bounds__(256) k_zero(const int* __restrict__ seg_res,
                                              const int* __restrict__ seg_atom,
                                              float* __restrict__ out) {
    __shared__ int s_as[2], s_ae[2];
    const int i0 = blockIdx.x * 2;
    if (threadIdx.x < 2) {
        const int b = seg_res[i0 + threadIdx.x];
        s_as[threadIdx.x] = lowerb(seg_atom, NA, b);
        s_ae[threadIdx.x] = lowerb(seg_atom, NA, b + 1);
    }
    __syncthreads();

    const float4 z4 = make_float4(0.f, 0.f, 0.f, 0.f);
    #pragma unroll
    for (int r = 0; r < 2; r++) {
        const int as = s_as[r], ae = s_ae[r];
        float4* out4 = reinterpret_cast<float4*>(out) + (size_t)(i0 + r) * (NA * H / 4);

        const int nl = as * (H / 4);
        for (int idx = threadIdx.x; idx < nl; idx += 256) __stcs(&out4[idx], z4);

        const int nr = (NA - ae) * (H / 4);
        float4* outr = out4 + ae * (H / 4);
        for (int idx = threadIdx.x; idx < nr; idx += 256) __stcs(&outr[idx], z4);
    }
}

// =================== Kernel T: tanh middles (after kA, || k_zero) ============
__global__ void __launch_bounds__(256) k_tanh(const int* __restrict__ seg_res,
                                              const float* __restrict__ tpos,
                                              const float* __restrict__ dpos,
                                              float* __restrict__ out) {
    const int i = blockIdx.x;
    const int b = seg_res[i];
    const int as = g_as[b], ae = g_ae[b];
    const int na = ae - as;
    if (na <= 0) return;

    __shared__ float s_tf[H];
    __shared__ float s_dn[NA];

    if (threadIdx.x < H) s_tf[threadIdx.x] = g_tf[i * H + threadIdx.x];

    const float px = tpos[3 * i], py = tpos[3 * i + 1], pz = tpos[3 * i + 2];
    const float dmin = g_dminf[b], inv = g_invden[b];
    for (int j = as + (int)threadIdx.x; j < ae; j += 256) {
        float dx = px - dpos[3 * j];
        float dy = py - dpos[3 * j + 1];
        float dz = pz - dpos[3 * j + 2];
        s_dn[j - as] = (sqrtf(dx * dx + dy * dy + dz * dz) - dmin) * inv;
    }
    __syncthreads();

    float4* outm = reinterpret_cast<float4*>(out) + (size_t)i * (NA * H / 4) + as * (H / 4);
    const float4* df4 = reinterpret_cast<const float4*>(g_df);
    const float4* tf4 = reinterpret_cast<const float4*>(s_tf);
    const int nm = na * (H / 4);
    for (int idx = threadIdx.x; idx < nm; idx += 256) {
        const int jo = idx >> 5;
        const int q  = idx & 31;
        const float dn = s_dn[jo];
        const float4 tv = tf4[q];
        const float4 dv = df4[(size_t)(as + jo) * 32 + q];
        float4 r;
        r.x = tanhf(tv.x - dv.x + dn);
        r.y = tanhf(tv.y - dv.y + dn);
        r.z = tanhf(tv.z - dv.z + dn);
        r.w = tanhf(tv.w - dv.w + dn);
        __stcs(&outm[idx], r);
    }
}

// ---------------- launch: (kA -> k_tanh) || k_zero, join at end ---------------
extern "C" void kernel_launch(void* const* d_in, const int* in_sizes, int n_in,
                              void* d_out, int out_size) {
    const float* target_feature = (const float*)d_in[0];
    const float* drug_feature   = (const float*)d_in[1];
    const float* target_pos     = (const float*)d_in[2];
    const float* drug_pos       = (const float*)d_in[3];
    const float* Wt             = (const float*)d_in[4];
    const float* bt             = (const float*)d_in[5];
    const float* Wd             = (const float*)d_in[6];
    const float* bd             = (const float*)d_in[7];
    const int*   seg_res        = (const int*)d_in[8];
    const int*   seg_atom       = (const int*)d_in[9];
    float* out = (float*)d_out;

    static cudaStream_t s_side = nullptr;
    static cudaEvent_t  e_fork = nullptr, e_join = nullptr;
    if (s_side == nullptr) {
        cudaStreamCreateWithFlags(&s_side, cudaStreamNonBlocking);
        cudaEventCreateWithFlags(&e_fork, cudaEventDisableTiming);
        cudaEventCreateWithFlags(&e_join, cudaEventDisableTiming);
        cudaFuncSetAttribute(kA, cudaFuncAttributeMaxDynamicSharedMemorySize, DYN_BYTES);
    }

    // fork: side stream runs kA then k_tanh, concurrent with k_zero on main.
    // k_tanh depends only on kA (stream order); its output stripes are
    // disjoint (512B-aligned) from k_zero's stripes.
    cudaEventRecord(e_fork, 0);
    cudaStreamWaitEvent(s_side, e_fork, 0);
    kA<<<NGEMM, 256, DYN_BYTES, s_side>>>(target_feature, Wt, bt,
                                          drug_feature, Wd, bd,
                                          target_pos, drug_pos,
                                          seg_res, seg_atom);
    k_tanh<<<NR, 256, 0, s_side>>>(seg_res, target_pos, drug_pos, out);
    cudaEventRecord(e_join, s_side);

    k_zero<<<NR / 2, 256>>>(seg_res, seg_atom, out);

    // join: graph completes only when both branches are done
    cudaStreamWaitEvent(0, e_join, 0);
}